// round 2
// baseline (speedup 1.0000x reference)
#include <cuda_runtime.h>
#include <cstdint>

#define N_NODES 50000
#define N_EDGES 800000
#define C 32
#define BN_EPS 1e-5f

// ---------------- device scratch (static: no allocations allowed) ----------
__device__ __align__(16) float g_A[N_NODES * C];          // x @ W1_top + b1
__device__ __align__(16) float g_B[N_NODES * C];          // x @ W1_bot
__device__ __align__(16) float g_y2[(size_t)N_EDGES * C]; // 102.4 MB pre-BN2 activations
__device__ float g_stat1[64];               // sum[32], sumsq[32] of y1
__device__ float g_stat2[64];               // sum[32], sumsq[32] of y2
__device__ __align__(16) float g_sc1[64];   // scale[32], shift[32] for BN1
__device__ __align__(16) float g_sc2[64];   // scale[32], shift[32] for BN2

__device__ __forceinline__ void red_add_v4(float* p, float a, float b, float c, float d) {
    asm volatile("red.global.add.v4.f32 [%0], {%1, %2, %3, %4};"
                 :: "l"(p), "f"(a), "f"(b), "f"(c), "f"(d) : "memory");
}

// ---------------- K0: zero output + stat accumulators ----------------------
__global__ void k0_zero(float* out) {
    int g = blockIdx.x * blockDim.x + threadIdx.x;
    int n = gridDim.x * blockDim.x;
    for (int i = g; i < N_NODES * C; i += n) out[i] = 0.f;
    if (g < 64) { g_stat1[g] = 0.f; g_stat2[g] = 0.f; }
}

// ---------------- K1: per-node precompute A = x@W1_top + b1, B = x@W1_bot --
__global__ void k1_node(const float* __restrict__ x, const float* __restrict__ W1,
                        const float* __restrict__ b1) {
    __shared__ float sW[2 * C * C]; // 2048 floats
    for (int i = threadIdx.x; i < 2 * C * C; i += blockDim.x) sW[i] = W1[i];
    __syncthreads();
    int warp = threadIdx.x >> 5, lane = threadIdx.x & 31;
    int node = blockIdx.x * (blockDim.x >> 5) + warp;
    if (node >= N_NODES) return;
    float xv = x[node * C + lane];
    float a = b1[lane], b = 0.f;
#pragma unroll
    for (int i = 0; i < C; i++) {
        float xi = __shfl_sync(0xffffffffu, xv, i);
        a = fmaf(xi, sW[i * C + lane], a);
        b = fmaf(xi, sW[(i + C) * C + lane], b);
    }
    g_A[node * C + lane] = a;
    g_B[node * C + lane] = b;
}

// ---------------- K2: per-channel sum/sumsq of y1 = A[row]+B[col] ----------
// 4 threads per edge, 8 channels each. Gathers hit L2 (tables = 12.8 MB).
__global__ void k2_stats1(const int* __restrict__ ei) {
    int g = blockIdx.x * blockDim.x + threadIdx.x;
    int nthr = gridDim.x * blockDim.x;
    int chunk = g & 3; // channels [chunk*8, chunk*8+8)
    float s[8], q[8];
#pragma unroll
    for (int i = 0; i < 8; i++) { s[i] = 0.f; q[i] = 0.f; }
    const float4* A4 = (const float4*)g_A;
    const float4* B4 = (const float4*)g_B;
    for (int e = g >> 2; e < N_EDGES; e += nthr >> 2) {
        int row = ei[e];
        int col = ei[N_EDGES + e];
        float4 a0 = A4[row * 8 + chunk * 2], a1 = A4[row * 8 + chunk * 2 + 1];
        float4 b0 = B4[col * 8 + chunk * 2], b1 = B4[col * 8 + chunk * 2 + 1];
        float y;
        y = a0.x + b0.x; s[0] += y; q[0] = fmaf(y, y, q[0]);
        y = a0.y + b0.y; s[1] += y; q[1] = fmaf(y, y, q[1]);
        y = a0.z + b0.z; s[2] += y; q[2] = fmaf(y, y, q[2]);
        y = a0.w + b0.w; s[3] += y; q[3] = fmaf(y, y, q[3]);
        y = a1.x + b1.x; s[4] += y; q[4] = fmaf(y, y, q[4]);
        y = a1.y + b1.y; s[5] += y; q[5] = fmaf(y, y, q[5]);
        y = a1.z + b1.z; s[6] += y; q[6] = fmaf(y, y, q[6]);
        y = a1.w + b1.w; s[7] += y; q[7] = fmaf(y, y, q[7]);
    }
#pragma unroll
    for (int off = 4; off < 32; off <<= 1) {
#pragma unroll
        for (int i = 0; i < 8; i++) {
            s[i] += __shfl_xor_sync(0xffffffffu, s[i], off);
            q[i] += __shfl_xor_sync(0xffffffffu, q[i], off);
        }
    }
    __shared__ float sh[64];
    if (threadIdx.x < 64) sh[threadIdx.x] = 0.f;
    __syncthreads();
    int lane = threadIdx.x & 31;
    if (lane < 4) {
#pragma unroll
        for (int i = 0; i < 8; i++) {
            atomicAdd(&sh[chunk * 8 + i], s[i]);
            atomicAdd(&sh[32 + chunk * 8 + i], q[i]);
        }
    }
    __syncthreads();
    if (threadIdx.x < 64) atomicAdd(&g_stat1[threadIdx.x], sh[threadIdx.x]);
}

// ---------------- finalize: BN fold to scale/shift (reads symbols directly) -
__global__ void k_finalize(const float* __restrict__ gamma, const float* __restrict__ beta,
                           int stage) {
    int c = threadIdx.x;
    if (c < C) {
        const float* stat = (stage == 1) ? g_stat1 : g_stat2;
        float* sc = (stage == 1) ? g_sc1 : g_sc2;
        const float invE = 1.f / (float)N_EDGES;
        float mean = stat[c] * invE;
        float var = stat[32 + c] * invE - mean * mean;
        float s = gamma[c] * rsqrtf(var + BN_EPS);
        sc[c] = s;
        sc[32 + c] = beta[c] - mean * s;
    }
}

// ---------------- K4: main edge pass: BN1+ReLU -> @W2+b2 -> store y2 -------
__global__ void __launch_bounds__(256) k4_main(const int* __restrict__ ei,
                                               const float* __restrict__ W2,
                                               const float* __restrict__ b2) {
    __shared__ __align__(16) float sW2[C * C];
    __shared__ float sS1[C], sT1[C], sB2[C];
    for (int i = threadIdx.x; i < C * C; i += blockDim.x) sW2[i] = W2[i];
    if (threadIdx.x < C) {
        sS1[threadIdx.x] = g_sc1[threadIdx.x];
        sT1[threadIdx.x] = g_sc1[32 + threadIdx.x];
        sB2[threadIdx.x] = b2[threadIdx.x];
    }
    __syncthreads();
    int e = blockIdx.x * blockDim.x + threadIdx.x; // grid sized exactly
    int row = ei[e];
    int col = ei[N_EDGES + e];
    float acc[C];
#pragma unroll
    for (int j = 0; j < C; j++) acc[j] = sB2[j];
    const float4* A4 = (const float4*)g_A;
    const float4* B4 = (const float4*)g_B;
    const float4* W4 = (const float4*)sW2;
#pragma unroll
    for (int k = 0; k < 8; k++) {
        float4 a = A4[row * 8 + k];
        float4 b = B4[col * 8 + k];
        float h[4];
        h[0] = fmaxf(fmaf(a.x + b.x, sS1[4 * k + 0], sT1[4 * k + 0]), 0.f);
        h[1] = fmaxf(fmaf(a.y + b.y, sS1[4 * k + 1], sT1[4 * k + 1]), 0.f);
        h[2] = fmaxf(fmaf(a.z + b.z, sS1[4 * k + 2], sT1[4 * k + 2]), 0.f);
        h[3] = fmaxf(fmaf(a.w + b.w, sS1[4 * k + 3], sT1[4 * k + 3]), 0.f);
#pragma unroll
        for (int u = 0; u < 4; u++) {
            int i = 4 * k + u;
#pragma unroll
            for (int qq = 0; qq < 8; qq++) {
                float4 w = W4[i * 8 + qq];
                acc[4 * qq + 0] = fmaf(h[u], w.x, acc[4 * qq + 0]);
                acc[4 * qq + 1] = fmaf(h[u], w.y, acc[4 * qq + 1]);
                acc[4 * qq + 2] = fmaf(h[u], w.z, acc[4 * qq + 2]);
                acc[4 * qq + 3] = fmaf(h[u], w.w, acc[4 * qq + 3]);
            }
        }
    }
    float4* Y4 = (float4*)(g_y2 + (size_t)e * C);
#pragma unroll
    for (int qq = 0; qq < 8; qq++)
        Y4[qq] = make_float4(acc[4 * qq], acc[4 * qq + 1], acc[4 * qq + 2], acc[4 * qq + 3]);
}

// ---------------- K5: per-channel sum/sumsq of y2 (linear scan) ------------
__global__ void k5_stats2() {
    int g = blockIdx.x * blockDim.x + threadIdx.x;
    int nthr = gridDim.x * blockDim.x;
    int chunk = g & 7; // channels [chunk*4, chunk*4+4)
    float s[4], q[4];
#pragma unroll
    for (int i = 0; i < 4; i++) { s[i] = 0.f; q[i] = 0.f; }
    const float4* Y4 = (const float4*)g_y2;
    for (int e = g >> 3; e < N_EDGES; e += nthr >> 3) {
        float4 v = Y4[(size_t)e * 8 + chunk];
        s[0] += v.x; q[0] = fmaf(v.x, v.x, q[0]);
        s[1] += v.y; q[1] = fmaf(v.y, v.y, q[1]);
        s[2] += v.z; q[2] = fmaf(v.z, v.z, q[2]);
        s[3] += v.w; q[3] = fmaf(v.w, v.w, q[3]);
    }
#pragma unroll
    for (int off = 8; off < 32; off <<= 1) {
#pragma unroll
        for (int i = 0; i < 4; i++) {
            s[i] += __shfl_xor_sync(0xffffffffu, s[i], off);
            q[i] += __shfl_xor_sync(0xffffffffu, q[i], off);
        }
    }
    __shared__ float sh[64];
    if (threadIdx.x < 64) sh[threadIdx.x] = 0.f;
    __syncthreads();
    int lane = threadIdx.x & 31;
    if (lane < 8) {
#pragma unroll
        for (int i = 0; i < 4; i++) {
            atomicAdd(&sh[chunk * 4 + i], s[i]);
            atomicAdd(&sh[32 + chunk * 4 + i], q[i]);
        }
    }
    __syncthreads();
    if (threadIdx.x < 64) atomicAdd(&g_stat2[threadIdx.x], sh[threadIdx.x]);
}

// ---------------- K7: BN2 + ReLU + vector scatter-add ----------------------
__global__ void k7_scatter(const int* __restrict__ ei, float* __restrict__ out) {
    int g = blockIdx.x * blockDim.x + threadIdx.x; // grid sized exactly E*8
    int e = g >> 3;
    int chunk = g & 7;
    int row = ei[e];
    const float4* Y4 = (const float4*)g_y2;
    float4 v = Y4[(size_t)e * 8 + chunk];
    float4 s2 = ((const float4*)g_sc2)[chunk];
    float4 t2 = ((const float4*)(g_sc2 + 32))[chunk];
    float h0 = fmaxf(fmaf(v.x, s2.x, t2.x), 0.f);
    float h1 = fmaxf(fmaf(v.y, s2.y, t2.y), 0.f);
    float h2 = fmaxf(fmaf(v.z, s2.z, t2.z), 0.f);
    float h3 = fmaxf(fmaf(v.w, s2.w, t2.w), 0.f);
    red_add_v4(out + row * C + chunk * 4, h0, h1, h2, h3);
}

// ---------------- launch ----------------------------------------------------
extern "C" void kernel_launch(void* const* d_in, const int* in_sizes, int n_in,
                              void* d_out, int out_size) {
    const float* x      = (const float*)d_in[0];
    const float* W1     = (const float*)d_in[1];
    const float* b1     = (const float*)d_in[2];
    const float* gamma1 = (const float*)d_in[3];
    const float* beta1  = (const float*)d_in[4];
    const float* W2     = (const float*)d_in[5];
    const float* b2     = (const float*)d_in[6];
    const float* gamma2 = (const float*)d_in[7];
    const float* beta2  = (const float*)d_in[8];
    const int* ei       = (const int*)d_in[9];   // jax x64 disabled -> int32
    float* out = (float*)d_out;

    k0_zero<<<1024, 256>>>(out);
    k1_node<<<N_NODES / 8, 256>>>(x, W1, b1);
    k2_stats1<<<2048, 256>>>(ei);
    k_finalize<<<1, 32>>>(gamma1, beta1, 1);
    k4_main<<<N_EDGES / 256, 256>>>(ei, W2, b2);
    k5_stats2<<<2048, 256>>>();
    k_finalize<<<1, 32>>>(gamma2, beta2, 2);
    k7_scatter<<<N_EDGES * 8 / 256, 256>>>(ei, out);
}

// round 3
// speedup vs baseline: 1.1122x; 1.1122x over previous
#include <cuda_runtime.h>
#include <cuda_fp16.h>
#include <cstdint>

#define N_NODES 50000
#define N_EDGES 800000
#define C 32
#define BN_EPS 1e-5f

typedef unsigned long long ull;

// ---------------- device scratch (static: no allocations allowed) ----------
__device__ __align__(16) float g_A[N_NODES * C];            // x @ W1_top + b1
__device__ __align__(16) float g_B[N_NODES * C];            // x @ W1_bot
__device__ __align__(16) __half g_y2h[(size_t)N_EDGES * C]; // 51.2 MB pre-BN2 (fp16)
__device__ float g_stat1[64];               // sum[32], sumsq[32] of y1
__device__ float g_stat2[64];               // sum[32], sumsq[32] of y2

__device__ __forceinline__ void red_add_v4(float* p, float a, float b, float c, float d) {
    asm volatile("red.global.add.v4.f32 [%0], {%1, %2, %3, %4};"
                 :: "l"(p), "f"(a), "f"(b), "f"(c), "f"(d) : "memory");
}
__device__ __forceinline__ ull pack2(float lo, float hi) {
    ull r; asm("mov.b64 %0, {%1, %2};" : "=l"(r) : "f"(lo), "f"(hi)); return r;
}
__device__ __forceinline__ float2 unpack2(ull v) {
    float2 f; asm("mov.b64 {%0, %1}, %2;" : "=f"(f.x), "=f"(f.y) : "l"(v)); return f;
}
__device__ __forceinline__ ull fma2(ull a, ull b, ull c) {
    ull d; asm("fma.rn.f32x2 %0, %1, %2, %3;" : "=l"(d) : "l"(a), "l"(b), "l"(c)); return d;
}

// ---------------- K0: zero output + stat accumulators ----------------------
__global__ void k0_zero(float* out) {
    int g = blockIdx.x * blockDim.x + threadIdx.x;
    int n = gridDim.x * blockDim.x;
    for (int i = g; i < N_NODES * C; i += n) out[i] = 0.f;
    if (g < 64) { g_stat1[g] = 0.f; g_stat2[g] = 0.f; }
}

// ---------------- K1: per-node precompute A = x@W1_top + b1, B = x@W1_bot --
__global__ void k1_node(const float* __restrict__ x, const float* __restrict__ W1,
                        const float* __restrict__ b1) {
    __shared__ float sW[2 * C * C];
    for (int i = threadIdx.x; i < 2 * C * C; i += blockDim.x) sW[i] = W1[i];
    __syncthreads();
    int warp = threadIdx.x >> 5, lane = threadIdx.x & 31;
    int node = blockIdx.x * (blockDim.x >> 5) + warp;
    if (node >= N_NODES) return;
    float xv = x[node * C + lane];
    float a = b1[lane], b = 0.f;
#pragma unroll
    for (int i = 0; i < C; i++) {
        float xi = __shfl_sync(0xffffffffu, xv, i);
        a = fmaf(xi, sW[i * C + lane], a);
        b = fmaf(xi, sW[(i + C) * C + lane], b);
    }
    g_A[node * C + lane] = a;
    g_B[node * C + lane] = b;
}

// ---------------- K2: per-channel sum/sumsq of y1 = A[row]+B[col] ----------
__global__ void k2_stats1(const int* __restrict__ ei) {
    int g = blockIdx.x * blockDim.x + threadIdx.x;
    int nthr = gridDim.x * blockDim.x;
    int chunk = g & 3;
    float s[8], q[8];
#pragma unroll
    for (int i = 0; i < 8; i++) { s[i] = 0.f; q[i] = 0.f; }
    const float4* A4 = (const float4*)g_A;
    const float4* B4 = (const float4*)g_B;
    for (int e = g >> 2; e < N_EDGES; e += nthr >> 2) {
        int row = ei[e];
        int col = ei[N_EDGES + e];
        float4 a0 = A4[row * 8 + chunk * 2], a1 = A4[row * 8 + chunk * 2 + 1];
        float4 b0 = B4[col * 8 + chunk * 2], b1 = B4[col * 8 + chunk * 2 + 1];
        float y;
        y = a0.x + b0.x; s[0] += y; q[0] = fmaf(y, y, q[0]);
        y = a0.y + b0.y; s[1] += y; q[1] = fmaf(y, y, q[1]);
        y = a0.z + b0.z; s[2] += y; q[2] = fmaf(y, y, q[2]);
        y = a0.w + b0.w; s[3] += y; q[3] = fmaf(y, y, q[3]);
        y = a1.x + b1.x; s[4] += y; q[4] = fmaf(y, y, q[4]);
        y = a1.y + b1.y; s[5] += y; q[5] = fmaf(y, y, q[5]);
        y = a1.z + b1.z; s[6] += y; q[6] = fmaf(y, y, q[6]);
        y = a1.w + b1.w; s[7] += y; q[7] = fmaf(y, y, q[7]);
    }
#pragma unroll
    for (int off = 4; off < 32; off <<= 1) {
#pragma unroll
        for (int i = 0; i < 8; i++) {
            s[i] += __shfl_xor_sync(0xffffffffu, s[i], off);
            q[i] += __shfl_xor_sync(0xffffffffu, q[i], off);
        }
    }
    __shared__ float sh[64];
    if (threadIdx.x < 64) sh[threadIdx.x] = 0.f;
    __syncthreads();
    int lane = threadIdx.x & 31;
    if (lane < 4) {
#pragma unroll
        for (int i = 0; i < 8; i++) {
            atomicAdd(&sh[chunk * 8 + i], s[i]);
            atomicAdd(&sh[32 + chunk * 8 + i], q[i]);
        }
    }
    __syncthreads();
    if (threadIdx.x < 64) atomicAdd(&g_stat1[threadIdx.x], sh[threadIdx.x]);
}

// ---------------- K4: BN1-fold prologue; BN1+ReLU -> @W2+b2 -> fp16 store --
__global__ void __launch_bounds__(256) k4_main(const int* __restrict__ ei,
                                               const float* __restrict__ W2,
                                               const float* __restrict__ b2,
                                               const float* __restrict__ gamma1,
                                               const float* __restrict__ beta1) {
    __shared__ __align__(16) float sW2[C * C];
    __shared__ float sS1[C], sT1[C], sB2[C];
    for (int i = threadIdx.x; i < C * C; i += blockDim.x) sW2[i] = W2[i];
    if (threadIdx.x < C) {
        int c = threadIdx.x;
        const float invE = 1.f / (float)N_EDGES;
        float mean = g_stat1[c] * invE;
        float var = g_stat1[32 + c] * invE - mean * mean;
        float s = gamma1[c] * rsqrtf(var + BN_EPS);
        sS1[c] = s;
        sT1[c] = beta1[c] - mean * s;
        sB2[c] = b2[c];
    }
    __syncthreads();
    int e = blockIdx.x * blockDim.x + threadIdx.x; // grid sized exactly
    int row = ei[e];
    int col = ei[N_EDGES + e];
    ull acc2[16]; // 16 packed f32x2 pairs = 32 output channels
#pragma unroll
    for (int p = 0; p < 16; p++) acc2[p] = pack2(sB2[2 * p], sB2[2 * p + 1]);
    const float4* A4 = (const float4*)g_A;
    const float4* B4 = (const float4*)g_B;
    const ulonglong2* W16 = (const ulonglong2*)sW2; // row i = [i*8 .. i*8+7]
#pragma unroll
    for (int k = 0; k < 8; k++) {
        float4 a = A4[row * 8 + k];
        float4 b = B4[col * 8 + k];
        float h[4];
        h[0] = fmaxf(fmaf(a.x + b.x, sS1[4 * k + 0], sT1[4 * k + 0]), 0.f);
        h[1] = fmaxf(fmaf(a.y + b.y, sS1[4 * k + 1], sT1[4 * k + 1]), 0.f);
        h[2] = fmaxf(fmaf(a.z + b.z, sS1[4 * k + 2], sT1[4 * k + 2]), 0.f);
        h[3] = fmaxf(fmaf(a.w + b.w, sS1[4 * k + 3], sT1[4 * k + 3]), 0.f);
#pragma unroll
        for (int u = 0; u < 4; u++) {
            int i = 4 * k + u;
            ull hh = pack2(h[u], h[u]);
#pragma unroll
            for (int q = 0; q < 8; q++) {
                ulonglong2 w = W16[i * 8 + q];
                acc2[2 * q + 0] = fma2(hh, w.x, acc2[2 * q + 0]);
                acc2[2 * q + 1] = fma2(hh, w.y, acc2[2 * q + 1]);
            }
        }
    }
    // convert 32 fp32 -> 32 fp16, store 64B
    uint4 outv[4];
    unsigned* ow = (unsigned*)outv;
#pragma unroll
    for (int p = 0; p < 16; p++) {
        float2 f = unpack2(acc2[p]);
        __half2 hh = __floats2half2_rn(f.x, f.y);
        ow[p] = *(unsigned*)&hh;
    }
    uint4* Y = (uint4*)(g_y2h + (size_t)e * C);
#pragma unroll
    for (int p = 0; p < 4; p++) Y[p] = outv[p];
}

// ---------------- K5: per-channel sum/sumsq of fp16 y2 ---------------------
__global__ void k5_stats2() {
    int g = blockIdx.x * blockDim.x + threadIdx.x;
    int nthr = gridDim.x * blockDim.x;
    int chunk = g & 3; // channels [chunk*8, chunk*8+8)
    float s[8], q[8];
#pragma unroll
    for (int i = 0; i < 8; i++) { s[i] = 0.f; q[i] = 0.f; }
    const uint4* Y = (const uint4*)g_y2h; // edge row = 4 uint4
    for (int e = g >> 2; e < N_EDGES; e += nthr >> 2) {
        uint4 v = Y[(size_t)e * 4 + chunk];
        const unsigned* w = (const unsigned*)&v;
#pragma unroll
        for (int p = 0; p < 4; p++) {
            float2 f = __half22float2(*(const __half2*)&w[p]);
            s[2 * p] += f.x;     q[2 * p] = fmaf(f.x, f.x, q[2 * p]);
            s[2 * p + 1] += f.y; q[2 * p + 1] = fmaf(f.y, f.y, q[2 * p + 1]);
        }
    }
#pragma unroll
    for (int off = 4; off < 32; off <<= 1) {
#pragma unroll
        for (int i = 0; i < 8; i++) {
            s[i] += __shfl_xor_sync(0xffffffffu, s[i], off);
            q[i] += __shfl_xor_sync(0xffffffffu, q[i], off);
        }
    }
    __shared__ float sh[64];
    if (threadIdx.x < 64) sh[threadIdx.x] = 0.f;
    __syncthreads();
    int lane = threadIdx.x & 31;
    if (lane < 4) {
#pragma unroll
        for (int i = 0; i < 8; i++) {
            atomicAdd(&sh[chunk * 8 + i], s[i]);
            atomicAdd(&sh[32 + chunk * 8 + i], q[i]);
        }
    }
    __syncthreads();
    if (threadIdx.x < 64) atomicAdd(&g_stat2[threadIdx.x], sh[threadIdx.x]);
}

// ---------------- K7: BN2-fold prologue; BN2+ReLU + vector scatter-add -----
__global__ void __launch_bounds__(256) k7_scatter(const int* __restrict__ ei,
                                                  const float* __restrict__ gamma2,
                                                  const float* __restrict__ beta2,
                                                  float* __restrict__ out) {
    __shared__ float sS2[C], sT2[C];
    if (threadIdx.x < C) {
        int c = threadIdx.x;
        const float invE = 1.f / (float)N_EDGES;
        float mean = g_stat2[c] * invE;
        float var = g_stat2[32 + c] * invE - mean * mean;
        float s = gamma2[c] * rsqrtf(var + BN_EPS);
        sS2[c] = s;
        sT2[c] = beta2[c] - mean * s;
    }
    __syncthreads();
    int g = blockIdx.x * blockDim.x + threadIdx.x; // grid sized exactly E*4
    int e = g >> 2;
    int chunk = g & 3; // 8 channels
    int row = ei[e];
    const uint4* Y = (const uint4*)g_y2h;
    uint4 v = Y[(size_t)e * 4 + chunk];
    const unsigned* w = (const unsigned*)&v;
    float h[8];
#pragma unroll
    for (int p = 0; p < 4; p++) {
        float2 f = __half22float2(*(const __half2*)&w[p]);
        int c = chunk * 8 + 2 * p;
        h[2 * p]     = fmaxf(fmaf(f.x, sS2[c],     sT2[c]),     0.f);
        h[2 * p + 1] = fmaxf(fmaf(f.y, sS2[c + 1], sT2[c + 1]), 0.f);
    }
    float* dst = out + row * C + chunk * 8;
    red_add_v4(dst,     h[0], h[1], h[2], h[3]);
    red_add_v4(dst + 4, h[4], h[5], h[6], h[7]);
}

// ---------------- launch ----------------------------------------------------
extern "C" void kernel_launch(void* const* d_in, const int* in_sizes, int n_in,
                              void* d_out, int out_size) {
    const float* x      = (const float*)d_in[0];
    const float* W1     = (const float*)d_in[1];
    const float* b1     = (const float*)d_in[2];
    const float* gamma1 = (const float*)d_in[3];
    const float* beta1  = (const float*)d_in[4];
    const float* W2     = (const float*)d_in[5];
    const float* b2     = (const float*)d_in[6];
    const float* gamma2 = (const float*)d_in[7];
    const float* beta2  = (const float*)d_in[8];
    const int* ei       = (const int*)d_in[9];
    float* out = (float*)d_out;

    k0_zero<<<1024, 256>>>(out);
    k1_node<<<N_NODES / 8, 256>>>(x, W1, b1);
    k2_stats1<<<2048, 256>>>(ei);
    k4_main<<<N_EDGES / 256, 256>>>(ei, W2, b2, gamma1, beta1);
    k5_stats2<<<2048, 256>>>();
    k7_scatter<<<N_EDGES * 4 / 256, 256>>>(ei, gamma2, beta2, out);
}

// round 4
// speedup vs baseline: 1.4763x; 1.3273x over previous
#include <cuda_runtime.h>
#include <cuda_fp16.h>
#include <cstdint>

#define N_NODES 50000
#define N_EDGES 800000
#define C 32
#define BN_EPS 1e-5f

typedef unsigned long long ull;

// ---------------- device scratch ----------------
__device__ __align__(16) float g_A[N_NODES * C];            // x @ W1_top + b1
__device__ __align__(16) float g_B[N_NODES * C];            // x @ W1_bot
__device__ __align__(16) __half g_y2h[(size_t)N_EDGES * C]; // 51.2 MB pre-BN2 (fp16)
__device__ float g_stat1[64];
__device__ float g_stat2[64];

__device__ __forceinline__ void red_add_v4(float* p, float a, float b, float c, float d) {
    asm volatile("red.global.add.v4.f32 [%0], {%1, %2, %3, %4};"
                 :: "l"(p), "f"(a), "f"(b), "f"(c), "f"(d) : "memory");
}
__device__ __forceinline__ ull pack2(float lo, float hi) {
    ull r; asm("mov.b64 %0, {%1, %2};" : "=l"(r) : "f"(lo), "f"(hi)); return r;
}
__device__ __forceinline__ float2 unpack2(ull v) {
    float2 f; asm("mov.b64 {%0, %1}, %2;" : "=f"(f.x), "=f"(f.y) : "l"(v)); return f;
}
__device__ __forceinline__ ull fma2(ull a, ull b, ull c) {
    ull d; asm("fma.rn.f32x2 %0, %1, %2, %3;" : "=l"(d) : "l"(a), "l"(b), "l"(c)); return d;
}

// ---------------- K1: zero out/stats + per-node precompute -----------------
__global__ void k1_node(const float* __restrict__ x, const float* __restrict__ W1,
                        const float* __restrict__ b1, float* __restrict__ out) {
    int g = blockIdx.x * blockDim.x + threadIdx.x;
    if (g < N_NODES * C) out[g] = 0.f;        // grid is 6250*256 = 1.6M = N_NODES*C exactly
    if (g < 64) { g_stat1[g] = 0.f; g_stat2[g] = 0.f; }

    __shared__ float sW[2 * C * C];
    for (int i = threadIdx.x; i < 2 * C * C; i += blockDim.x) sW[i] = W1[i];
    __syncthreads();
    int warp = threadIdx.x >> 5, lane = threadIdx.x & 31;
    int node = blockIdx.x * (blockDim.x >> 5) + warp;
    if (node >= N_NODES) return;
    float xv = x[node * C + lane];
    float a = b1[lane], b = 0.f;
#pragma unroll
    for (int i = 0; i < C; i++) {
        float xi = __shfl_sync(0xffffffffu, xv, i);
        a = fmaf(xi, sW[i * C + lane], a);
        b = fmaf(xi, sW[(i + C) * C + lane], b);
    }
    g_A[node * C + lane] = a;
    g_B[node * C + lane] = b;
}

// ---------------- K2: per-channel sum/sumsq of y1 = A[row]+B[col] ----------
__global__ void k2_stats1(const int* __restrict__ ei) {
    int g = blockIdx.x * blockDim.x + threadIdx.x;
    int nthr = gridDim.x * blockDim.x;
    int chunk = g & 3;
    float s[8], q[8];
#pragma unroll
    for (int i = 0; i < 8; i++) { s[i] = 0.f; q[i] = 0.f; }
    const float4* A4 = (const float4*)g_A;
    const float4* B4 = (const float4*)g_B;
    for (int e = g >> 2; e < N_EDGES; e += nthr >> 2) {
        int row = ei[e];
        int col = ei[N_EDGES + e];
        float4 a0 = A4[row * 8 + chunk * 2], a1 = A4[row * 8 + chunk * 2 + 1];
        float4 b0 = B4[col * 8 + chunk * 2], b1 = B4[col * 8 + chunk * 2 + 1];
        float y;
        y = a0.x + b0.x; s[0] += y; q[0] = fmaf(y, y, q[0]);
        y = a0.y + b0.y; s[1] += y; q[1] = fmaf(y, y, q[1]);
        y = a0.z + b0.z; s[2] += y; q[2] = fmaf(y, y, q[2]);
        y = a0.w + b0.w; s[3] += y; q[3] = fmaf(y, y, q[3]);
        y = a1.x + b1.x; s[4] += y; q[4] = fmaf(y, y, q[4]);
        y = a1.y + b1.y; s[5] += y; q[5] = fmaf(y, y, q[5]);
        y = a1.z + b1.z; s[6] += y; q[6] = fmaf(y, y, q[6]);
        y = a1.w + b1.w; s[7] += y; q[7] = fmaf(y, y, q[7]);
    }
#pragma unroll
    for (int off = 4; off < 32; off <<= 1) {
#pragma unroll
        for (int i = 0; i < 8; i++) {
            s[i] += __shfl_xor_sync(0xffffffffu, s[i], off);
            q[i] += __shfl_xor_sync(0xffffffffu, q[i], off);
        }
    }
    __shared__ float sh[64];
    if (threadIdx.x < 64) sh[threadIdx.x] = 0.f;
    __syncthreads();
    int lane = threadIdx.x & 31;
    if (lane < 4) {
#pragma unroll
        for (int i = 0; i < 8; i++) {
            atomicAdd(&sh[chunk * 8 + i], s[i]);
            atomicAdd(&sh[32 + chunk * 8 + i], q[i]);
        }
    }
    __syncthreads();
    if (threadIdx.x < 64) atomicAdd(&g_stat1[threadIdx.x], sh[threadIdx.x]);
}

// ---------------- K4: coalesced gather -> SMEM -> 2-edge GEMM + stats2 -----
// 128 threads, 256 edges per block, grid = 3125 (exact).
#define HS 33  // padded h-tile stride (floats)
__global__ void __launch_bounds__(128, 4) k4_main(const int* __restrict__ ei,
                                                  const float* __restrict__ W2,
                                                  const float* __restrict__ b2,
                                                  const float* __restrict__ gamma1,
                                                  const float* __restrict__ beta1) {
    __shared__ __align__(16) float sW2[C * C];
    __shared__ float sh_h[256 * HS];
    __shared__ float sS1[C], sT1[C], sB2[C];
    __shared__ float sh_st[4 * 64];
    int tid = threadIdx.x;
    for (int i = tid; i < C * C; i += blockDim.x) sW2[i] = W2[i];
    if (tid < C) {
        const float invE = 1.f / (float)N_EDGES;
        float mean = g_stat1[tid] * invE;
        float var = g_stat1[32 + tid] * invE - mean * mean;
        float s = gamma1[tid] * rsqrtf(var + BN_EPS);
        sS1[tid] = s;
        sT1[tid] = beta1[tid] - mean * s;
        sB2[tid] = b2[tid];
    }
    __syncthreads();

    // ---- phase 1: coalesced gather + BN1 + ReLU -> fp32 SMEM tile ----
    int q = tid & 3;                 // which 8-channel slice
    const float4* A4 = (const float4*)g_A;
    const float4* B4 = (const float4*)g_B;
    float s1v[8], t1v[8];
#pragma unroll
    for (int j = 0; j < 8; j++) { s1v[j] = sS1[q * 8 + j]; t1v[j] = sT1[q * 8 + j]; }
#pragma unroll
    for (int r = 0; r < 8; r++) {
        int el = (tid >> 2) + r * 32;            // local edge 0..255
        int e = blockIdx.x * 256 + el;
        int row = ei[e];
        int col = ei[N_EDGES + e];
        float4 a0 = A4[row * 8 + q * 2], a1 = A4[row * 8 + q * 2 + 1];
        float4 b0 = B4[col * 8 + q * 2], b1 = B4[col * 8 + q * 2 + 1];
        float* hrow = sh_h + el * HS + q * 8;
        hrow[0] = fmaxf(fmaf(a0.x + b0.x, s1v[0], t1v[0]), 0.f);
        hrow[1] = fmaxf(fmaf(a0.y + b0.y, s1v[1], t1v[1]), 0.f);
        hrow[2] = fmaxf(fmaf(a0.z + b0.z, s1v[2], t1v[2]), 0.f);
        hrow[3] = fmaxf(fmaf(a0.w + b0.w, s1v[3], t1v[3]), 0.f);
        hrow[4] = fmaxf(fmaf(a1.x + b1.x, s1v[4], t1v[4]), 0.f);
        hrow[5] = fmaxf(fmaf(a1.y + b1.y, s1v[5], t1v[5]), 0.f);
        hrow[6] = fmaxf(fmaf(a1.z + b1.z, s1v[6], t1v[6]), 0.f);
        hrow[7] = fmaxf(fmaf(a1.w + b1.w, s1v[7], t1v[7]), 0.f);
    }
    __syncthreads();

    // ---- phase 2: 2 edges per thread, f32x2 GEMM ----
    ull accA[16], accB[16];
#pragma unroll
    for (int p = 0; p < 16; p++) {
        ull init = pack2(sB2[2 * p], sB2[2 * p + 1]);
        accA[p] = init; accB[p] = init;
    }
    const ulonglong2* W16 = (const ulonglong2*)sW2;
    const float* hA = sh_h + tid * HS;
    const float* hB = sh_h + (tid + 128) * HS;
#pragma unroll
    for (int i = 0; i < C; i++) {
        ull ha = pack2(hA[i], hA[i]);
        ull hb = pack2(hB[i], hB[i]);
#pragma unroll
        for (int qq = 0; qq < 8; qq++) {
            ulonglong2 w = W16[i * 8 + qq];
            accA[2 * qq]     = fma2(ha, w.x, accA[2 * qq]);
            accA[2 * qq + 1] = fma2(ha, w.y, accA[2 * qq + 1]);
            accB[2 * qq]     = fma2(hb, w.x, accB[2 * qq]);
            accB[2 * qq + 1] = fma2(hb, w.y, accB[2 * qq + 1]);
        }
    }

    // ---- store y2 (fp16) + accumulate stats2 ----
    float s[32], sq[32];
    uint4 ovA[4], ovB[4];
    unsigned* owA = (unsigned*)ovA;
    unsigned* owB = (unsigned*)ovB;
#pragma unroll
    for (int p = 0; p < 16; p++) {
        float2 fA = unpack2(accA[p]);
        float2 fB = unpack2(accB[p]);
        __half2 hhA = __floats2half2_rn(fA.x, fA.y);
        __half2 hhB = __floats2half2_rn(fB.x, fB.y);
        owA[p] = *(unsigned*)&hhA;
        owB[p] = *(unsigned*)&hhB;
        s[2 * p]      = fA.x + fB.x;
        s[2 * p + 1]  = fA.y + fB.y;
        sq[2 * p]     = fmaf(fA.x, fA.x, fB.x * fB.x);
        sq[2 * p + 1] = fmaf(fA.y, fA.y, fB.y * fB.y);
    }
    size_t gA = (size_t)blockIdx.x * 256 + tid;
    size_t gB = gA + 128;
    uint4* Y = (uint4*)g_y2h;
#pragma unroll
    for (int p = 0; p < 4; p++) { Y[gA * 4 + p] = ovA[p]; Y[gB * 4 + p] = ovB[p]; }

    // warp butterfly reduce (all lanes end with warp totals)
#pragma unroll
    for (int off = 1; off < 32; off <<= 1) {
#pragma unroll
        for (int j = 0; j < 32; j++) {
            s[j]  += __shfl_xor_sync(0xffffffffu, s[j], off);
            sq[j] += __shfl_xor_sync(0xffffffffu, sq[j], off);
        }
    }
    int warp = tid >> 5, lane = tid & 31;
    if (lane == 0) {
#pragma unroll
        for (int j = 0; j < 32; j++) {
            sh_st[warp * 64 + j] = s[j];
            sh_st[warp * 64 + 32 + j] = sq[j];
        }
    }
    __syncthreads();
    if (tid < 64) {
        float v = sh_st[tid] + sh_st[64 + tid] + sh_st[128 + tid] + sh_st[192 + tid];
        atomicAdd(&g_stat2[tid], v);
    }
}

// ---------------- K7: BN2-fold prologue; BN2+ReLU + vector scatter-add -----
__global__ void __launch_bounds__(256) k7_scatter(const int* __restrict__ ei,
                                                  const float* __restrict__ gamma2,
                                                  const float* __restrict__ beta2,
                                                  float* __restrict__ out) {
    __shared__ float sS2[C], sT2[C];
    if (threadIdx.x < C) {
        int c = threadIdx.x;
        const float invE = 1.f / (float)N_EDGES;
        float mean = g_stat2[c] * invE;
        float var = g_stat2[32 + c] * invE - mean * mean;
        float s = gamma2[c] * rsqrtf(var + BN_EPS);
        sS2[c] = s;
        sT2[c] = beta2[c] - mean * s;
    }
    __syncthreads();
    int g = blockIdx.x * blockDim.x + threadIdx.x; // grid sized exactly E*4
    int e = g >> 2;
    int chunk = g & 3; // 8 channels
    int row = ei[e];
    const uint4* Y = (const uint4*)g_y2h;
    uint4 v = Y[(size_t)e * 4 + chunk];
    const unsigned* w = (const unsigned*)&v;
    float h[8];
#pragma unroll
    for (int p = 0; p < 4; p++) {
        float2 f = __half22float2(*(const __half2*)&w[p]);
        int c = chunk * 8 + 2 * p;
        h[2 * p]     = fmaxf(fmaf(f.x, sS2[c],     sT2[c]),     0.f);
        h[2 * p + 1] = fmaxf(fmaf(f.y, sS2[c + 1], sT2[c + 1]), 0.f);
    }
    float* dst = out + row * C + chunk * 8;
    red_add_v4(dst,     h[0], h[1], h[2], h[3]);
    red_add_v4(dst + 4, h[4], h[5], h[6], h[7]);
}

// ---------------- launch ----------------------------------------------------
extern "C" void kernel_launch(void* const* d_in, const int* in_sizes, int n_in,
                              void* d_out, int out_size) {
    const float* x      = (const float*)d_in[0];
    const float* W1     = (const float*)d_in[1];
    const float* b1     = (const float*)d_in[2];
    const float* gamma1 = (const float*)d_in[3];
    const float* beta1  = (const float*)d_in[4];
    const float* W2     = (const float*)d_in[5];
    const float* b2     = (const float*)d_in[6];
    const float* gamma2 = (const float*)d_in[7];
    const float* beta2  = (const float*)d_in[8];
    const int* ei       = (const int*)d_in[9];
    float* out = (float*)d_out;

    k1_node<<<N_NODES / 8, 256>>>(x, W1, b1, out);     // 6250 blocks
    k2_stats1<<<2048, 256>>>(ei);
    k4_main<<<N_EDGES / 256, 128>>>(ei, W2, b2, gamma1, beta1); // 3125 blocks
    k7_scatter<<<N_EDGES * 4 / 256, 256>>>(ei, gamma2, beta2, out);
}